// round 14
// baseline (speedup 1.0000x reference)
#include <cuda_runtime.h>
#include <cuda_fp16.h>
#include <mma.h>
#include <cstdint>

using namespace nvcuda;

#define NN 100000
#define NE 600000
#define C 128
#define OC 64
#define NREL 3
#define HLD 136    // fp16 tile stride (halves) -> 272B rows
#define FLD 132    // f32 tile stride (floats)
#define TM 64      // nodes per CTA tile

// smem layout (bytes)
#define OX   0        // X fp16 [64][HLD]            17408
#define OQ   17408    // A fp16 [64][HLD]            17408
#define OP   34816    // A f32 staging [64][128]     32768
#define OW0  67584    // W buf0: Wl q + Wr q         17408
#define OW1  84992    // W buf1                      17408
#define OCNT 102400   // cnt staging [2][64] f32     512
#define SMEMF 102912
#define WQB  8704     // one 32-row fp16 quarter [32][HLD] bytes

// ---------------- scratch (static device globals) ---------------------------
__device__ float  g_agg[(size_t)NREL * NN * C];
__device__ float  g_cnt[NREL * NN];
__device__ __half g_xh[(size_t)NN * C];
__device__ float  g_t[(size_t)NN * OC];
__device__ float  g_aggF[(size_t)NN * OC];
__device__ float  g_po[(size_t)NN * OC];
__device__ __half g_Whl[NREL * C * C];
__device__ __half g_Whr[NREL * C * C];
__device__ __half g_Whf[C * C];               // [Wlf | Wrf] fp16 [k][n]
__device__ float  g_iota[16 * 16];

__device__ __forceinline__ uint32_t h2u(__half2 h) {
    return *reinterpret_cast<uint32_t*>(&h);
}
__device__ __forceinline__ void red_add_v4(float* p, float4 v) {
    asm volatile("red.global.add.v4.f32 [%0], {%1, %2, %3, %4};"
                 :: "l"(p), "f"(v.x), "f"(v.y), "f"(v.z), "f"(v.w) : "memory");
}
__device__ __forceinline__ uint32_t smem_u32(const void* p) {
    uint32_t a;
    asm("{ .reg .u64 t; cvta.to.shared.u64 t, %1; cvt.u32.u64 %0, t; }"
        : "=r"(a) : "l"(p));
    return a;
}
__device__ __forceinline__ void cpa16(uint32_t dst, const void* src) {
    asm volatile("cp.async.ca.shared.global [%0], [%1], 16;"
                 :: "r"(dst), "l"(src) : "memory");
}
__device__ __forceinline__ void cpa16z(uint32_t dst, const void* src, bool ok) {
    int sz = ok ? 16 : 0;
    asm volatile("cp.async.ca.shared.global [%0], [%1], 16, %2;"
                 :: "r"(dst), "l"(src), "r"(sz) : "memory");
}
#define CPA_COMMIT() asm volatile("cp.async.commit_group;" ::: "memory")
#define CPA_WAIT1()  asm volatile("cp.async.wait_group 1;" ::: "memory")

// ---------------- kernel P: fp16 weights + iota + x->fp16 -------------------
__global__ void k_prep(const float* __restrict__ Wl, const float* __restrict__ Wr,
                       const float* __restrict__ Wlf, const float* __restrict__ Wrf,
                       const float* __restrict__ x) {
    int i0 = blockIdx.x * blockDim.x + threadIdx.x;
    int stride = gridDim.x * blockDim.x;
    for (int i = i0; i < NREL * C * C; i += stride) {
        g_Whl[i] = __float2half(Wl[i]);
        g_Whr[i] = __float2half(Wr[i]);
    }
    for (int i = i0; i < C * C; i += stride) {
        int n = i & (C - 1), k = i >> 7;
        float v = (n < OC) ? Wlf[k * OC + n] : Wrf[k * OC + (n - OC)];
        g_Whf[i] = __float2half(v);
    }
    for (int i = i0; i < 256; i += stride)
        g_iota[i] = (float)(i & 15);
    int n8 = NN * C / 8;
    for (int i = i0; i < n8; i += stride) {
        float4 a = *reinterpret_cast<const float4*>(x + (size_t)i * 8);
        float4 b = *reinterpret_cast<const float4*>(x + (size_t)i * 8 + 4);
        uint4 o;
        o.x = h2u(__floats2half2_rn(a.x, a.y));
        o.y = h2u(__floats2half2_rn(a.z, a.w));
        o.z = h2u(__floats2half2_rn(b.x, b.y));
        o.w = h2u(__floats2half2_rn(b.z, b.w));
        *reinterpret_cast<uint4*>(g_xh + (size_t)i * 8) = o;
    }
}

// ---------------- kernel 1: scatter x, 4 edges per warp (R8 measured) -------
__global__ void k_scatter_x(const float* __restrict__ x,
                            const int* __restrict__ ei0,
                            const int* __restrict__ ei1,
                            const int* __restrict__ ei2) {
    int r = blockIdx.y;
    const int* ei = (r == 0) ? ei0 : (r == 1) ? ei1 : ei2;
    int w = (blockIdx.x * blockDim.x + threadIdx.x) >> 5;
    int lane = threadIdx.x & 31;
    int e0 = w * 4;
    if (e0 >= NE) return;
    int s[4], d[4];
    bool ok[4];
#pragma unroll
    for (int e = 0; e < 4; e++) {
        s[e] = ei[e0 + e];
        d[e] = ei[NE + e0 + e];
        ok[e] = ((unsigned)s[e] < NN) && ((unsigned)d[e] < NN);
    }
    float4 v[4];
#pragma unroll
    for (int e = 0; e < 4; e++)
        if (ok[e])
            v[e] = *reinterpret_cast<const float4*>(x + (size_t)s[e] * C + lane * 4);
#pragma unroll
    for (int e = 0; e < 4; e++)
        if (ok[e])
            red_add_v4(g_agg + (size_t)r * NN * C + (size_t)d[e] * C + lane * 4, v[e]);
    if (lane < 4 && ok[lane])
        atomicAdd(&g_cnt[r * NN + d[lane]], 1.f);
}

// ---------------- fused deep-pipelined fp16 WMMA GEMM -----------------------
// 64-node tiles, 256 thr (8 warps, 2x4 of 32x32), 2 CTAs/SM.
// 12 steps (3 rel x 4 K-quarters). W double-buffered; A f32 prefetched one
// relation ahead via cp.async into P, converted smem->smem to fp16 tile Q.
__global__ __launch_bounds__(256, 2)
void k_gemm_fused(const float* __restrict__ bl, const float* __restrict__ blf) {
    extern __shared__ char sm[];
    __shared__ float bls[NREL * C + OC];
    __half* X_s  = reinterpret_cast<__half*>(sm + OX);
    __half* Q_s  = reinterpret_cast<__half*>(sm + OQ);
    float*  P_s  = reinterpret_cast<float*>(sm + OP);
    float*  cbuf = reinterpret_cast<float*>(sm + OCNT);
    float*  H32  = reinterpret_cast<float*>(sm);          // [64][FLD] over X+Q
    __half* Hh   = reinterpret_cast<__half*>(sm + OP);    // [64][HLD] over P
    float*  Df   = reinterpret_cast<float*>(sm);          // [64][FLD] over X+Q

    uint32_t base = smem_u32(sm);
    int tid = threadIdx.x;
    int wid = tid >> 5;
    int node0 = blockIdx.x * TM;
    int wm = (wid >> 2) * 32;
    int wn = (wid & 3) * 32;

    for (int i = tid; i < NREL * C; i += 256) bls[i] = bl[i];
    if (tid < OC) bls[NREL * C + tid] = blf[tid];

    // ---- prologue group C0: X, A0 (f32), cnt0, W(step 0 quarter) ----
    for (int it = tid; it < TM * 16; it += 256) {
        int row = it >> 4, c = it & 15;
        int node = node0 + row;
        cpa16z(base + OX + row * 272 + c * 16,
               g_xh + (size_t)node * C + c * 8, node < NN);
    }
    for (int it = tid; it < TM * 32; it += 256) {
        int row = it >> 5, c = it & 31;
        int node = node0 + row;
        cpa16z(base + OP + row * 512 + c * 16,
               g_agg + (size_t)node * C + c * 4, node < NN);
    }
    if (tid < 16)
        cpa16z(base + OCNT + tid * 16, g_cnt + node0 + tid * 4,
               (node0 + tid * 4) < NN);
    for (int it = tid; it < 32 * 16; it += 256) {
        int row = it >> 4, c = it & 15;
        cpa16(base + OW0 + row * 272 + c * 16, g_Whl + row * C + c * 8);
        cpa16(base + OW0 + WQB + row * 272 + c * 16, g_Whr + row * C + c * 8);
    }
    CPA_COMMIT();  // C0

    wmma::fragment<wmma::accumulator, 16, 16, 16, float> iotaf;
    wmma::load_matrix_sync(iotaf, g_iota, 16, wmma::mem_row_major);

    wmma::fragment<wmma::accumulator, 16, 16, 16, float> hfrag[2][2];
#pragma unroll
    for (int i = 0; i < 2; i++)
#pragma unroll
        for (int j = 0; j < 2; j++) wmma::fill_fragment(hfrag[i][j], 0.f);
    const float inv3 = 1.f / 3.f;

    wmma::fragment<wmma::accumulator, 16, 16, 16, float> acc[2][2];

    for (int s = 0; s < 12; s++) {
        int r = s >> 2, q = s & 3;
        __syncthreads();  // previous step's MMAs / conversions done

        // prefetch next W quarter (or first Wf quarter at s==11)
        if (s < 11) {
            int s2 = s + 1, r2 = s2 >> 2, q2 = s2 & 3;
            const __half* wl = g_Whl + (size_t)r2 * C * C + q2 * 32 * C;
            const __half* wr = g_Whr + (size_t)r2 * C * C + q2 * 32 * C;
            uint32_t wb = base + ((s2 & 1) ? OW1 : OW0);
            for (int it = tid; it < 32 * 16; it += 256) {
                int row = it >> 4, c = it & 15;
                cpa16(wb + row * 272 + c * 16, wl + row * C + c * 8);
                cpa16(wb + WQB + row * 272 + c * 16, wr + row * C + c * 8);
            }
        } else {
            for (int it = tid; it < 32 * 16; it += 256) {
                int row = it >> 4, c = it & 15;
                cpa16(base + OW0 + row * 272 + c * 16, g_Whf + row * C + c * 8);
            }
        }
        // at q==1: P is free (converted at q==0) -> prefetch next relation's A
        if (q == 1 && r < 2) {
            int rn = r + 1;
            const float* aggr = g_agg + (size_t)rn * NN * C;
            for (int it = tid; it < TM * 32; it += 256) {
                int row = it >> 5, c = it & 31;
                int node = node0 + row;
                cpa16z(base + OP + row * 512 + c * 16,
                       aggr + (size_t)node * C + c * 4, node < NN);
            }
            if (tid < 16)
                cpa16z(base + OCNT + (rn & 1) * 256 + tid * 16,
                       g_cnt + rn * NN + node0 + tid * 4,
                       (node0 + tid * 4) < NN);
        }
        CPA_COMMIT();
        CPA_WAIT1();  // this thread's groups (except newest) complete

        if (q == 0) {
            // FIX (R13 bug): cross-thread visibility barrier for cnt staging.
            // wait_group is per-thread; cbuf was written by threads 0..15 but
            // is read by all 256 — must barrier after the wait before reading.
            __syncthreads();
            // convert P (f32, smem) -> Q (fp16 tile), scaled by 1/max(cnt,1)
            const float* cb = cbuf + (r & 1) * 64;
            float4 va[8];
            int rows[8], cs[8];
#pragma unroll
            for (int i = 0; i < 8; i++) {
                int idx = tid + i * 256;
                rows[i] = idx >> 5;
                cs[i]   = idx & 31;
                va[i] = *reinterpret_cast<const float4*>(
                    P_s + rows[i] * 128 + cs[i] * 4);
            }
#pragma unroll
            for (int i = 0; i < 8; i++) {
                float iv = 1.f / fmaxf(cb[rows[i]], 1.f);
                __half2* dp = reinterpret_cast<__half2*>(
                    Q_s + rows[i] * HLD + cs[i] * 4);
                dp[0] = __floats2half2_rn(va[i].x * iv, va[i].y * iv);
                dp[1] = __floats2half2_rn(va[i].z * iv, va[i].w * iv);
            }
#pragma unroll
            for (int i = 0; i < 2; i++)
#pragma unroll
                for (int j = 0; j < 2; j++) wmma::fill_fragment(acc[i][j], 0.f);
        }
        __syncthreads();  // W + Q visible to all warps

        __half* WlS = reinterpret_cast<__half*>(sm + ((s & 1) ? OW1 : OW0));
        __half* WrS = WlS + WQB / 2;
#pragma unroll
        for (int ks = 0; ks < 2; ks++) {
            int kloc = ks * 16;
            int kglb = q * 32 + kloc;
            wmma::fragment<wmma::matrix_a, 16, 16, 16, __half,
                           wmma::row_major> af[2], xf[2];
            wmma::fragment<wmma::matrix_b, 16, 16, 16, __half,
                           wmma::row_major> lf[2], rf[2];
#pragma unroll
            for (int i = 0; i < 2; i++) {
                wmma::load_matrix_sync(af[i], Q_s + (wm + i * 16) * HLD + kglb, HLD);
                wmma::load_matrix_sync(xf[i], X_s + (wm + i * 16) * HLD + kglb, HLD);
            }
#pragma unroll
            for (int j = 0; j < 2; j++) {
                wmma::load_matrix_sync(lf[j], WlS + kloc * HLD + wn + j * 16, HLD);
                wmma::load_matrix_sync(rf[j], WrS + kloc * HLD + wn + j * 16, HLD);
            }
#pragma unroll
            for (int i = 0; i < 2; i++)
#pragma unroll
                for (int j = 0; j < 2; j++) {
                    wmma::mma_sync(acc[i][j], af[i], lf[j], acc[i][j]);
                    wmma::mma_sync(acc[i][j], xf[i], rf[j], acc[i][j]);
                }
        }

        if (q == 3) {
#pragma unroll
            for (int i = 0; i < 2; i++)
#pragma unroll
                for (int j = 0; j < 2; j++)
#pragma unroll
                    for (int t = 0; t < 8; t++) {
                        float b = bls[r * C + wn + j * 16 + (int)iotaf.x[t]];
                        hfrag[i][j].x[t] +=
                            fmaxf(acc[i][j].x[t] + b, 0.f) * inv3;
                    }
        }
    }

    // ---------------- final GEMM: D_f = h @ [Wlf | Wrf] ---------------------
    __syncthreads();  // step-11 MMAs done; X/Q/P dead
#pragma unroll
    for (int i = 0; i < 2; i++)
#pragma unroll
        for (int j = 0; j < 2; j++)
            wmma::store_matrix_sync(H32 + (wm + i * 16) * FLD + wn + j * 16,
                                    hfrag[i][j], FLD, wmma::mem_row_major);
    __syncthreads();
    for (int it = tid; it < TM * 64; it += 256) {
        int row = it >> 6, c2 = it & 63;
        float2 v = *reinterpret_cast<const float2*>(H32 + row * FLD + c2 * 2);
        *reinterpret_cast<__half2*>(Hh + row * HLD + c2 * 2) =
            __floats2half2_rn(v.x, v.y);
    }

    wmma::fragment<wmma::accumulator, 16, 16, 16, float> acc2[2][2];
#pragma unroll
    for (int i = 0; i < 2; i++)
#pragma unroll
        for (int j = 0; j < 2; j++) wmma::fill_fragment(acc2[i][j], 0.f);

    for (int f = 0; f < 4; f++) {
        __syncthreads();  // prev f's MMAs done (f==0: Hh writes done)
        if (f < 3) {
            const __half* wf = g_Whf + (size_t)(f + 1) * 32 * C;
            uint32_t wb = base + (((f + 1) & 1) ? OW1 : OW0);
            for (int it = tid; it < 32 * 16; it += 256) {
                int row = it >> 4, c = it & 15;
                cpa16(wb + row * 272 + c * 16, wf + row * C + c * 8);
            }
        }
        CPA_COMMIT();
        CPA_WAIT1();
        __syncthreads();

        __half* WfS = reinterpret_cast<__half*>(sm + ((f & 1) ? OW1 : OW0));
#pragma unroll
        for (int ks = 0; ks < 2; ks++) {
            int kloc = ks * 16;
            int k = f * 32 + kloc;
            wmma::fragment<wmma::matrix_a, 16, 16, 16, __half,
                           wmma::row_major> hf[2];
            wmma::fragment<wmma::matrix_b, 16, 16, 16, __half,
                           wmma::row_major> wf2[2];
#pragma unroll
            for (int i = 0; i < 2; i++)
                wmma::load_matrix_sync(hf[i], Hh + (wm + i * 16) * HLD + k, HLD);
#pragma unroll
            for (int j = 0; j < 2; j++)
                wmma::load_matrix_sync(wf2[j], WfS + kloc * HLD + wn + j * 16, HLD);
#pragma unroll
            for (int i = 0; i < 2; i++)
#pragma unroll
                for (int j = 0; j < 2; j++)
                    wmma::mma_sync(acc2[i][j], hf[i], wf2[j], acc2[i][j]);
        }
    }

    __syncthreads();  // H32 region consumed (Hh conversion) -> reuse for Df
#pragma unroll
    for (int i = 0; i < 2; i++)
#pragma unroll
        for (int j = 0; j < 2; j++)
            wmma::store_matrix_sync(Df + (wm + i * 16) * FLD + wn + j * 16,
                                    acc2[i][j], FLD, wmma::mem_row_major);
    __syncthreads();

    // epilogue: t (cols 0..63), po (cols 64..127, +blf); zero aggF slice
    {
        int row = tid >> 2;
        int ec  = (tid & 3) * 32;
        int node = node0 + row;
        if (node < NN) {
            if (ec < OC) {
                float* tp = g_t + (size_t)node * OC + ec;
                float* zp = g_aggF + (size_t)node * OC + ec;
#pragma unroll
                for (int qq = 0; qq < 8; qq++) {
                    *reinterpret_cast<float4*>(tp + qq * 4) =
                        *reinterpret_cast<const float4*>(Df + row * FLD + ec + qq * 4);
                    *reinterpret_cast<float4*>(zp + qq * 4) =
                        make_float4(0.f, 0.f, 0.f, 0.f);
                }
            } else {
                float* pp = g_po + (size_t)node * OC + (ec - OC);
                float* zp = g_aggF + (size_t)node * OC + (ec - OC);
#pragma unroll
                for (int qq = 0; qq < 8; qq++) {
                    float4 d = *reinterpret_cast<const float4*>(
                        Df + row * FLD + ec + qq * 4);
                    const float* b = bls + NREL * C + (ec - OC) + qq * 4;
                    *reinterpret_cast<float4*>(pp + qq * 4) = make_float4(
                        d.x + b[0], d.y + b[1], d.z + b[2], d.w + b[3]);
                    *reinterpret_cast<float4*>(zp + qq * 4) =
                        make_float4(0.f, 0.f, 0.f, 0.f);
                }
            }
        }
    }
}

// ---------------- kernel 4: scatter t, 4 edges per half-warp (R8 measured) --
__global__ void k_scatter_t(const int* __restrict__ ei) {
    int hw = (blockIdx.x * blockDim.x + threadIdx.x) >> 4;
    int lane = threadIdx.x & 15;
    int e0 = hw * 4;
    if (e0 >= NE) return;
    int s[4], d[4];
    bool ok[4];
#pragma unroll
    for (int e = 0; e < 4; e++) {
        s[e] = ei[e0 + e];
        d[e] = ei[NE + e0 + e];
        ok[e] = ((unsigned)s[e] < NN) && ((unsigned)d[e] < NN);
    }
    float4 v[4];
#pragma unroll
    for (int e = 0; e < 4; e++)
        if (ok[e])
            v[e] = *reinterpret_cast<const float4*>(g_t + (size_t)s[e] * OC + lane * 4);
#pragma unroll
    for (int e = 0; e < 4; e++)
        if (ok[e])
            red_add_v4(g_aggF + (size_t)d[e] * OC + lane * 4, v[e]);
}

// ---------------- kernel 5: out = aggF / max(cnt0,1) + po -------------------
__global__ void k_final(float* __restrict__ out) {
    int i = blockIdx.x * blockDim.x + threadIdx.x;
    int stride = gridDim.x * blockDim.x;
    int n4 = NN * OC / 4;
    const float4* a4 = reinterpret_cast<const float4*>(g_aggF);
    const float4* p4 = reinterpret_cast<const float4*>(g_po);
    float4* o4 = reinterpret_cast<float4*>(out);
    for (int j = i; j < n4; j += stride) {
        int node = j / (OC / 4);
        float inv = 1.f / fmaxf(g_cnt[node], 1.f);
        float4 a = a4[j];
        float4 p = p4[j];
        o4[j] = make_float4(a.x * inv + p.x, a.y * inv + p.y,
                            a.z * inv + p.z, a.w * inv + p.w);
    }
}

// ---------------- launch ----------------------------------------------------
extern "C" void kernel_launch(void* const* d_in, const int* in_sizes, int n_in,
                              void* d_out, int out_size) {
    const float* x   = (const float*)d_in[0];
    const float* Wl  = (const float*)d_in[1];
    const float* bl  = (const float*)d_in[2];
    const float* Wr  = (const float*)d_in[3];
    const float* Wlf = (const float*)d_in[4];
    const float* blf = (const float*)d_in[5];
    const float* Wrf = (const float*)d_in[6];
    const int* ei0   = (const int*)d_in[7];
    const int* ei1   = (const int*)d_in[8];
    const int* ei2   = (const int*)d_in[9];
    float* out = (float*)d_out;

    void *pagg, *pcnt;
    cudaGetSymbolAddress(&pagg, g_agg);
    cudaGetSymbolAddress(&pcnt, g_cnt);
    cudaMemsetAsync(pagg, 0, (size_t)NREL * NN * C * sizeof(float), 0);
    cudaMemsetAsync(pcnt, 0, (size_t)NREL * NN * sizeof(float), 0);

    k_prep<<<1024, 256>>>(Wl, Wr, Wlf, Wrf, x);

    dim3 sgrid((NE / 4 + 7) / 8, 3);
    k_scatter_x<<<sgrid, 256>>>(x, ei0, ei1, ei2);

    cudaFuncSetAttribute(k_gemm_fused, cudaFuncAttributeMaxDynamicSharedMemorySize, SMEMF);
    int gb = (NN + TM - 1) / TM;  // 1563
    k_gemm_fused<<<gb, 256, SMEMF>>>(bl, blf);

    k_scatter_t<<<(NE / 4 + 15) / 16, 256>>>(ei0);
    k_final<<<2048, 256>>>(out);
}

// round 15
// speedup vs baseline: 1.0142x; 1.0142x over previous
#include <cuda_runtime.h>
#include <cuda_fp16.h>
#include <mma.h>
#include <cstdint>

using namespace nvcuda;

#define NN 100000
#define NE 600000
#define C 128
#define OC 64
#define NREL 3
#define HLD 136    // fp16 tile stride (halves) -> 272B rows
#define FLD 132    // f32 tile stride (floats)
#define TM 64      // nodes per CTA tile
#define WHB 17408  // bytes of one 64-row fp16 half-matrix [64][HLD]

// ---------------- scratch (static device globals) ---------------------------
__device__ float  g_agg[(size_t)NREL * NN * C];
__device__ float  g_cnt[NREL * NN];
__device__ __half g_xh[(size_t)NN * C];
__device__ float  g_t[(size_t)NN * OC];
__device__ float  g_aggF[(size_t)NN * OC];
__device__ float  g_po[(size_t)NN * OC];
__device__ __half g_Whl[NREL * C * C];
__device__ __half g_Whr[NREL * C * C];
__device__ __half g_Whf[C * C];               // [Wlf | Wrf] fp16 [k][n]
__device__ float  g_iota[16 * 16];

__device__ __forceinline__ uint32_t h2u(__half2 h) {
    return *reinterpret_cast<uint32_t*>(&h);
}
__device__ __forceinline__ void red_add_v4(float* p, float4 v) {
    asm volatile("red.global.add.v4.f32 [%0], {%1, %2, %3, %4};"
                 :: "l"(p), "f"(v.x), "f"(v.y), "f"(v.z), "f"(v.w) : "memory");
}
__device__ __forceinline__ uint32_t smem_u32(const void* p) {
    uint32_t a;
    asm("{ .reg .u64 t; cvta.to.shared.u64 t, %1; cvt.u32.u64 %0, t; }"
        : "=r"(a) : "l"(p));
    return a;
}
__device__ __forceinline__ void cpa16(uint32_t dst, const void* src) {
    asm volatile("cp.async.ca.shared.global [%0], [%1], 16;"
                 :: "r"(dst), "l"(src) : "memory");
}
__device__ __forceinline__ void cpa16z(uint32_t dst, const void* src, bool ok) {
    int sz = ok ? 16 : 0;
    asm volatile("cp.async.ca.shared.global [%0], [%1], 16, %2;"
                 :: "r"(dst), "l"(src), "r"(sz) : "memory");
}
#define CPA_COMMIT() asm volatile("cp.async.commit_group;" ::: "memory")
#define CPA_WAIT0()  asm volatile("cp.async.wait_group 0;" ::: "memory")
#define CPA_WAIT1()  asm volatile("cp.async.wait_group 1;" ::: "memory")

// ---------------- kernel P: fp16 weights + iota + x->fp16 -------------------
__global__ void k_prep(const float* __restrict__ Wl, const float* __restrict__ Wr,
                       const float* __restrict__ Wlf, const float* __restrict__ Wrf,
                       const float* __restrict__ x) {
    int i0 = blockIdx.x * blockDim.x + threadIdx.x;
    int stride = gridDim.x * blockDim.x;
    for (int i = i0; i < NREL * C * C; i += stride) {
        g_Whl[i] = __float2half(Wl[i]);
        g_Whr[i] = __float2half(Wr[i]);
    }
    for (int i = i0; i < C * C; i += stride) {
        int n = i & (C - 1), k = i >> 7;
        float v = (n < OC) ? Wlf[k * OC + n] : Wrf[k * OC + (n - OC)];
        g_Whf[i] = __float2half(v);
    }
    for (int i = i0; i < 256; i += stride)
        g_iota[i] = (float)(i & 15);
    int n8 = NN * C / 8;
    for (int i = i0; i < n8; i += stride) {
        float4 a = *reinterpret_cast<const float4*>(x + (size_t)i * 8);
        float4 b = *reinterpret_cast<const float4*>(x + (size_t)i * 8 + 4);
        uint4 o;
        o.x = h2u(__floats2half2_rn(a.x, a.y));
        o.y = h2u(__floats2half2_rn(a.z, a.w));
        o.z = h2u(__floats2half2_rn(b.x, b.y));
        o.w = h2u(__floats2half2_rn(b.z, b.w));
        *reinterpret_cast<uint4*>(g_xh + (size_t)i * 8) = o;
    }
}

// ---------------- kernel 1: scatter x, 4 edges per warp (R8 measured) -------
__global__ void k_scatter_x(const float* __restrict__ x,
                            const int* __restrict__ ei0,
                            const int* __restrict__ ei1,
                            const int* __restrict__ ei2) {
    int r = blockIdx.y;
    const int* ei = (r == 0) ? ei0 : (r == 1) ? ei1 : ei2;
    int w = (blockIdx.x * blockDim.x + threadIdx.x) >> 5;
    int lane = threadIdx.x & 31;
    int e0 = w * 4;
    if (e0 >= NE) return;
    int s[4], d[4];
    bool ok[4];
#pragma unroll
    for (int e = 0; e < 4; e++) {
        s[e] = ei[e0 + e];
        d[e] = ei[NE + e0 + e];
        ok[e] = ((unsigned)s[e] < NN) && ((unsigned)d[e] < NN);
    }
    float4 v[4];
#pragma unroll
    for (int e = 0; e < 4; e++)
        if (ok[e])
            v[e] = *reinterpret_cast<const float4*>(x + (size_t)s[e] * C + lane * 4);
#pragma unroll
    for (int e = 0; e < 4; e++)
        if (ok[e])
            red_add_v4(g_agg + (size_t)r * NN * C + (size_t)d[e] * C + lane * 4, v[e]);
    if (lane < 4 && ok[lane])
        atomicAdd(&g_cnt[r * NN + d[lane]], 1.f);
}

// ---------------- fused pipelined fp16 WMMA GEMM (R12, 457-us measured) -----
// 64-node tiles, 256 thr (8 warps, 2x4 of 32x32), 2 CTAs/SM.
// 6 steps (3 rel x 2 K-halves), W double-buffered via cp.async.
__global__ __launch_bounds__(256, 2)
void k_gemm_fused(const float* __restrict__ bl, const float* __restrict__ blf) {
    extern __shared__ char smraw[];
    __shared__ float bls[NREL * C + OC];
    __half* X_s = reinterpret_cast<__half*>(smraw);      // [64][HLD]
    __half* A_s = X_s + TM * HLD;                        // [64][HLD]
    float*  H32 = reinterpret_cast<float*>(smraw);       // [64][FLD] over X+A
    float*  Df  = reinterpret_cast<float*>(smraw);       // [64][FLD] over X+A
    __half* WfS = reinterpret_cast<__half*>(smraw + 2 * WHB);  // over buf0 [128][HLD]
    __half* Hh  = reinterpret_cast<__half*>(smraw + 4 * WHB);  // over buf1 [64][HLD]

    uint32_t base = smem_u32(smraw);
    uint32_t xa = base;
    uint32_t wb0 = base + 2 * WHB;
    uint32_t wb1 = base + 4 * WHB;

    int tid = threadIdx.x;
    int wid = tid >> 5;
    int node0 = blockIdx.x * TM;
    int wm = (wid >> 2) * 32;
    int wn = (wid & 3) * 32;

    for (int i = tid; i < NREL * C; i += 256) bls[i] = bl[i];
    if (tid < OC) bls[NREL * C + tid] = blf[tid];

    // prologue: X tile + W(step 0 = rel0 half0) into buf0
    for (int it = tid; it < TM * 16; it += 256) {
        int row = it >> 4, c = it & 15;
        int node = node0 + row;
        bool ok = node < NN;
        cpa16z(xa + row * (HLD * 2) + c * 16,
               g_xh + (size_t)(ok ? node : 0) * C + c * 8, ok);
    }
    for (int it = tid; it < 64 * 16; it += 256) {
        int row = it >> 4, c = it & 15;
        cpa16(wb0 + row * (HLD * 2) + c * 16, g_Whl + row * C + c * 8);
        cpa16(wb0 + WHB + row * (HLD * 2) + c * 16, g_Whr + row * C + c * 8);
    }
    CPA_COMMIT();

    wmma::fragment<wmma::accumulator, 16, 16, 16, float> iotaf;
    wmma::load_matrix_sync(iotaf, g_iota, 16, wmma::mem_row_major);

    wmma::fragment<wmma::accumulator, 16, 16, 16, float> hfrag[2][2];
#pragma unroll
    for (int i = 0; i < 2; i++)
#pragma unroll
        for (int j = 0; j < 2; j++) wmma::fill_fragment(hfrag[i][j], 0.f);
    const float inv3 = 1.f / 3.f;

    wmma::fragment<wmma::accumulator, 16, 16, 16, float> acc[2][2];

    for (int s = 0; s < 6; s++) {
        int r = s >> 1, h = s & 1;
        __half* WlS = reinterpret_cast<__half*>(smraw + 2 * WHB + (s & 1) * 2 * WHB);
        __half* WrS = WlS + 64 * HLD;

        __syncthreads();  // all warps done with previous step's MMAs

        // prefetch next step's W into the other buffer
        if (s < 5) {
            int r2 = (s + 1) >> 1, h2 = (s + 1) & 1;
            const __half* wl = g_Whl + (size_t)r2 * C * C + h2 * 64 * C;
            const __half* wr = g_Whr + (size_t)r2 * C * C + h2 * 64 * C;
            uint32_t b = ((s + 1) & 1) ? wb1 : wb0;
            for (int it = tid; it < 64 * 16; it += 256) {
                int row = it >> 4, c = it & 15;
                cpa16(b + row * (HLD * 2) + c * 16, wl + row * C + c * 8);
                cpa16(b + WHB + row * (HLD * 2) + c * 16, wr + row * C + c * 8);
            }
        } else {
            for (int it = tid; it < 128 * 16; it += 256) {
                int row = it >> 4, c = it & 15;
                cpa16(wb0 + row * (HLD * 2) + c * 16, g_Whf + row * C + c * 8);
            }
        }
        CPA_COMMIT();

        if (h == 0) {
            // stage A tile for relation r (register-batched loads)
            const float* aggr = g_agg + (size_t)r * NN * C;
            const float* cntr = g_cnt + r * NN;
            float4 va[8];
            float  vc[8];
            bool   okr[8];
#pragma unroll
            for (int i = 0; i < 8; i++) {
                int idx = tid + i * 256;
                int row = idx >> 5, c4 = idx & 31;
                int node = node0 + row;
                okr[i] = node < NN;
                if (okr[i]) {
                    va[i] = *reinterpret_cast<const float4*>(
                        aggr + (size_t)node * C + c4 * 4);
                    vc[i] = cntr[node];
                }
            }
#pragma unroll
            for (int i = 0; i < 8; i++) {
                int idx = tid + i * 256;
                int row = idx >> 5, c4 = idx & 31;
                float4 v = make_float4(0.f, 0.f, 0.f, 0.f);
                if (okr[i]) {
                    float inv = 1.f / fmaxf(vc[i], 1.f);
                    v.x = va[i].x * inv; v.y = va[i].y * inv;
                    v.z = va[i].z * inv; v.w = va[i].w * inv;
                }
                __half2* dp = reinterpret_cast<__half2*>(A_s + row * HLD + c4 * 4);
                dp[0] = __floats2half2_rn(v.x, v.y);
                dp[1] = __floats2half2_rn(v.z, v.w);
            }
#pragma unroll
            for (int i = 0; i < 2; i++)
#pragma unroll
                for (int j = 0; j < 2; j++) wmma::fill_fragment(acc[i][j], 0.f);
        }

        CPA_WAIT1();      // current step's W group complete (next stays pending)
        __syncthreads();  // W + A visible to all warps

#pragma unroll
        for (int ks = 0; ks < 4; ks++) {
            int kloc = ks * 16;
            int kglb = h * 64 + kloc;
            wmma::fragment<wmma::matrix_a, 16, 16, 16, __half,
                           wmma::row_major> af[2], xf[2];
            wmma::fragment<wmma::matrix_b, 16, 16, 16, __half,
                           wmma::row_major> lf[2], rf[2];
#pragma unroll
            for (int i = 0; i < 2; i++) {
                wmma::load_matrix_sync(af[i], A_s + (wm + i * 16) * HLD + kglb, HLD);
                wmma::load_matrix_sync(xf[i], X_s + (wm + i * 16) * HLD + kglb, HLD);
            }
#pragma unroll
            for (int j = 0; j < 2; j++) {
                wmma::load_matrix_sync(lf[j], WlS + kloc * HLD + wn + j * 16, HLD);
                wmma::load_matrix_sync(rf[j], WrS + kloc * HLD + wn + j * 16, HLD);
            }
#pragma unroll
            for (int i = 0; i < 2; i++)
#pragma unroll
                for (int j = 0; j < 2; j++) {
                    wmma::mma_sync(acc[i][j], af[i], lf[j], acc[i][j]);
                    wmma::mma_sync(acc[i][j], xf[i], rf[j], acc[i][j]);
                }
        }

        if (h == 1) {
#pragma unroll
            for (int i = 0; i < 2; i++)
#pragma unroll
                for (int j = 0; j < 2; j++)
#pragma unroll
                    for (int t = 0; t < 8; t++) {
                        float b = bls[r * C + wn + j * 16 + (int)iotaf.x[t]];
                        hfrag[i][j].x[t] +=
                            fmaxf(acc[i][j].x[t] + b, 0.f) * inv3;
                    }
        }
    }

    // ---------------- final GEMM: D_f = h @ [Wlf | Wrf] ---------------------
    __syncthreads();  // all warps past step-5 MMAs (X/A/buf1 free)
#pragma unroll
    for (int i = 0; i < 2; i++)
#pragma unroll
        for (int j = 0; j < 2; j++)
            wmma::store_matrix_sync(H32 + (wm + i * 16) * FLD + wn + j * 16,
                                    hfrag[i][j], FLD, wmma::mem_row_major);
    __syncthreads();
    for (int it = tid; it < TM * 64; it += 256) {
        int row = it >> 6, c2 = it & 63;
        float2 v = *reinterpret_cast<const float2*>(H32 + row * FLD + c2 * 2);
        *reinterpret_cast<__half2*>(Hh + row * HLD + c2 * 2) =
            __floats2half2_rn(v.x, v.y);
    }
    CPA_WAIT0();      // Wf (prefetched during step 5) in buf0
    __syncthreads();

    {
        wmma::fragment<wmma::accumulator, 16, 16, 16, float> acc2[2][2];
#pragma unroll
        for (int i = 0; i < 2; i++)
#pragma unroll
            for (int j = 0; j < 2; j++) wmma::fill_fragment(acc2[i][j], 0.f);

#pragma unroll
        for (int ks = 0; ks < 8; ks++) {
            int k = ks * 16;
            wmma::fragment<wmma::matrix_a, 16, 16, 16, __half,
                           wmma::row_major> hf[2];
            wmma::fragment<wmma::matrix_b, 16, 16, 16, __half,
                           wmma::row_major> wf[2];
#pragma unroll
            for (int i = 0; i < 2; i++)
                wmma::load_matrix_sync(hf[i], Hh + (wm + i * 16) * HLD + k, HLD);
#pragma unroll
            for (int j = 0; j < 2; j++)
                wmma::load_matrix_sync(wf[j], WfS + k * HLD + wn + j * 16, HLD);
#pragma unroll
            for (int i = 0; i < 2; i++)
#pragma unroll
                for (int j = 0; j < 2; j++)
                    wmma::mma_sync(acc2[i][j], hf[i], wf[j], acc2[i][j]);
        }
        __syncthreads();  // H32 region free for Df
#pragma unroll
        for (int i = 0; i < 2; i++)
#pragma unroll
            for (int j = 0; j < 2; j++)
                wmma::store_matrix_sync(Df + (wm + i * 16) * FLD + wn + j * 16,
                                        acc2[i][j], FLD, wmma::mem_row_major);
        __syncthreads();
    }

    // epilogue: t (cols 0..63), po (cols 64..127, +blf); zero aggF slice
    {
        int row = tid >> 2;
        int ec  = (tid & 3) * 32;
        int node = node0 + row;
        if (node < NN) {
            if (ec < OC) {
                float* tp = g_t + (size_t)node * OC + ec;
                float* zp = g_aggF + (size_t)node * OC + ec;
#pragma unroll
                for (int q = 0; q < 8; q++) {
                    *reinterpret_cast<float4*>(tp + q * 4) =
                        *reinterpret_cast<const float4*>(Df + row * FLD + ec + q * 4);
                    *reinterpret_cast<float4*>(zp + q * 4) =
                        make_float4(0.f, 0.f, 0.f, 0.f);
                }
            } else {
                float* pp = g_po + (size_t)node * OC + (ec - OC);
                float* zp = g_aggF + (size_t)node * OC + (ec - OC);
#pragma unroll
                for (int q = 0; q < 8; q++) {
                    float4 d = *reinterpret_cast<const float4*>(
                        Df + row * FLD + ec + q * 4);
                    const float* b = bls + NREL * C + (ec - OC) + q * 4;
                    *reinterpret_cast<float4*>(pp + q * 4) = make_float4(
                        d.x + b[0], d.y + b[1], d.z + b[2], d.w + b[3]);
                    *reinterpret_cast<float4*>(zp + q * 4) =
                        make_float4(0.f, 0.f, 0.f, 0.f);
                }
            }
        }
    }
}

// ---------------- kernel 4: scatter t, 4 edges per half-warp (R8 measured) --
__global__ void k_scatter_t(const int* __restrict__ ei) {
    int hw = (blockIdx.x * blockDim.x + threadIdx.x) >> 4;
    int lane = threadIdx.x & 15;
    int e0 = hw * 4;
    if (e0 >= NE) return;
    int s[4], d[4];
    bool ok[4];
#pragma unroll
    for (int e = 0; e < 4; e++) {
        s[e] = ei[e0 + e];
        d[e] = ei[NE + e0 + e];
        ok[e] = ((unsigned)s[e] < NN) && ((unsigned)d[e] < NN);
    }
    float4 v[4];
#pragma unroll
    for (int e = 0; e < 4; e++)
        if (ok[e])
            v[e] = *reinterpret_cast<const float4*>(g_t + (size_t)s[e] * OC + lane * 4);
#pragma unroll
    for (int e = 0; e < 4; e++)
        if (ok[e])
            red_add_v4(g_aggF + (size_t)d[e] * OC + lane * 4, v[e]);
}

// ---------------- kernel 5: out = aggF / max(cnt0,1) + po -------------------
__global__ void k_final(float* __restrict__ out) {
    int i = blockIdx.x * blockDim.x + threadIdx.x;
    int stride = gridDim.x * blockDim.x;
    int n4 = NN * OC / 4;
    const float4* a4 = reinterpret_cast<const float4*>(g_aggF);
    const float4* p4 = reinterpret_cast<const float4*>(g_po);
    float4* o4 = reinterpret_cast<float4*>(out);
    for (int j = i; j < n4; j += stride) {
        int node = j / (OC / 4);
        float inv = 1.f / fmaxf(g_cnt[node], 1.f);
        float4 a = a4[j];
        float4 p = p4[j];
        o4[j] = make_float4(a.x * inv + p.x, a.y * inv + p.y,
                            a.z * inv + p.z, a.w * inv + p.w);
    }
}

// ---------------- launch ----------------------------------------------------
extern "C" void kernel_launch(void* const* d_in, const int* in_sizes, int n_in,
                              void* d_out, int out_size) {
    const float* x   = (const float*)d_in[0];
    const float* Wl  = (const float*)d_in[1];
    const float* bl  = (const float*)d_in[2];
    const float* Wr  = (const float*)d_in[3];
    const float* Wlf = (const float*)d_in[4];
    const float* blf = (const float*)d_in[5];
    const float* Wrf = (const float*)d_in[6];
    const int* ei0   = (const int*)d_in[7];
    const int* ei1   = (const int*)d_in[8];
    const int* ei2   = (const int*)d_in[9];
    float* out = (float*)d_out;

    // fork: k_prep runs on a side stream, overlapped with memsets + scatter_x.
    // Stream/events are created per call (host-side only; no device allocation)
    // and intentionally not destroyed here — destroying a stream mid-capture
    // is illegal, and kernel_launch only executes host-side twice.
    cudaStream_t s1;
    cudaEvent_t eFork, eJoin;
    cudaStreamCreateWithFlags(&s1, cudaStreamNonBlocking);
    cudaEventCreateWithFlags(&eFork, cudaEventDisableTiming);
    cudaEventCreateWithFlags(&eJoin, cudaEventDisableTiming);

    cudaEventRecord(eFork, 0);
    cudaStreamWaitEvent(s1, eFork, 0);
    k_prep<<<1024, 256, 0, s1>>>(Wl, Wr, Wlf, Wrf, x);
    cudaEventRecord(eJoin, s1);

    void *pagg, *pcnt;
    cudaGetSymbolAddress(&pagg, g_agg);
    cudaGetSymbolAddress(&pcnt, g_cnt);
    cudaMemsetAsync(pagg, 0, (size_t)NREL * NN * C * sizeof(float), 0);
    cudaMemsetAsync(pcnt, 0, (size_t)NREL * NN * sizeof(float), 0);

    dim3 sgrid((NE / 4 + 7) / 8, 3);
    k_scatter_x<<<sgrid, 256>>>(x, ei0, ei1, ei2);

    cudaStreamWaitEvent(0, eJoin, 0);  // gemm needs g_Whl/g_Whr/g_Whf/g_xh/iota

    const int SMEMF = 6 * WHB;  // X + A + 2 W half-buffers = 104448
    cudaFuncSetAttribute(k_gemm_fused, cudaFuncAttributeMaxDynamicSharedMemorySize, SMEMF);
    int gb = (NN + TM - 1) / TM;  // 1563
    k_gemm_fused<<<gb, 256, SMEMF>>>(bl, blf);

    k_scatter_t<<<(NE / 4 + 15) / 16, 256>>>(ei0);
    k_final<<<2048, 256>>>(out);
}

// round 16
// speedup vs baseline: 1.0243x; 1.0099x over previous
#include <cuda_runtime.h>
#include <cuda_fp16.h>
#include <mma.h>
#include <cstdint>

using namespace nvcuda;

#define NN 100000
#define NE 600000
#define C 128
#define OC 64
#define NREL 3
#define HLD 136    // fp16 tile stride (halves) -> 272B rows
#define FLD 132    // f32 tile stride (floats)
#define TM 64      // nodes per CTA tile
#define WHB 17408  // bytes of one 64-row fp16 half-matrix [64][HLD]

// ---------------- scratch (static device globals; zero-init at load) --------
// INVARIANT: g_agg and g_cnt are zero at kernel_launch entry. First call:
// CUDA zero-initializes __device__ globals. Subsequent calls/replays: the
// tail of this launch re-zeroes them (g_agg on a side stream concurrent with
// scatter_t/final; g_cnt after k_final which reads it). Same work + same
// output every call.
__device__ float  g_agg[(size_t)NREL * NN * C];
__device__ float  g_cnt[NREL * NN];
__device__ __half g_xh[(size_t)NN * C];
__device__ float  g_t[(size_t)NN * OC];
__device__ float  g_aggF[(size_t)NN * OC];
__device__ float  g_po[(size_t)NN * OC];
__device__ __half g_Whl[NREL * C * C];
__device__ __half g_Whr[NREL * C * C];
__device__ __half g_Whf[C * C];               // [Wlf | Wrf] fp16 [k][n]
__device__ float  g_iota[16 * 16];

__device__ __forceinline__ uint32_t h2u(__half2 h) {
    return *reinterpret_cast<uint32_t*>(&h);
}
__device__ __forceinline__ void red_add_v4(float* p, float4 v) {
    asm volatile("red.global.add.v4.f32 [%0], {%1, %2, %3, %4};"
                 :: "l"(p), "f"(v.x), "f"(v.y), "f"(v.z), "f"(v.w) : "memory");
}
__device__ __forceinline__ uint32_t smem_u32(const void* p) {
    uint32_t a;
    asm("{ .reg .u64 t; cvta.to.shared.u64 t, %1; cvt.u32.u64 %0, t; }"
        : "=r"(a) : "l"(p));
    return a;
}
__device__ __forceinline__ void cpa16(uint32_t dst, const void* src) {
    asm volatile("cp.async.ca.shared.global [%0], [%1], 16;"
                 :: "r"(dst), "l"(src) : "memory");
}
__device__ __forceinline__ void cpa16z(uint32_t dst, const void* src, bool ok) {
    int sz = ok ? 16 : 0;
    asm volatile("cp.async.ca.shared.global [%0], [%1], 16, %2;"
                 :: "r"(dst), "l"(src), "r"(sz) : "memory");
}
#define CPA_COMMIT() asm volatile("cp.async.commit_group;" ::: "memory")
#define CPA_WAIT0()  asm volatile("cp.async.wait_group 0;" ::: "memory")
#define CPA_WAIT1()  asm volatile("cp.async.wait_group 1;" ::: "memory")

// ---------------- kernel P: fp16 weights + iota + x->fp16 -------------------
__global__ void k_prep(const float* __restrict__ Wl, const float* __restrict__ Wr,
                       const float* __restrict__ Wlf, const float* __restrict__ Wrf,
                       const float* __restrict__ x) {
    int i0 = blockIdx.x * blockDim.x + threadIdx.x;
    int stride = gridDim.x * blockDim.x;
    for (int i = i0; i < NREL * C * C; i += stride) {
        g_Whl[i] = __float2half(Wl[i]);
        g_Whr[i] = __float2half(Wr[i]);
    }
    for (int i = i0; i < C * C; i += stride) {
        int n = i & (C - 1), k = i >> 7;
        float v = (n < OC) ? Wlf[k * OC + n] : Wrf[k * OC + (n - OC)];
        g_Whf[i] = __float2half(v);
    }
    for (int i = i0; i < 256; i += stride)
        g_iota[i] = (float)(i & 15);
    int n8 = NN * C / 8;
    for (int i = i0; i < n8; i += stride) {
        float4 a = *reinterpret_cast<const float4*>(x + (size_t)i * 8);
        float4 b = *reinterpret_cast<const float4*>(x + (size_t)i * 8 + 4);
        uint4 o;
        o.x = h2u(__floats2half2_rn(a.x, a.y));
        o.y = h2u(__floats2half2_rn(a.z, a.w));
        o.z = h2u(__floats2half2_rn(b.x, b.y));
        o.w = h2u(__floats2half2_rn(b.z, b.w));
        *reinterpret_cast<uint4*>(g_xh + (size_t)i * 8) = o;
    }
}

// ---------------- kernel 1: scatter x, 4 edges per warp (R8 measured) -------
__global__ void k_scatter_x(const float* __restrict__ x,
                            const int* __restrict__ ei0,
                            const int* __restrict__ ei1,
                            const int* __restrict__ ei2) {
    int r = blockIdx.y;
    const int* ei = (r == 0) ? ei0 : (r == 1) ? ei1 : ei2;
    int w = (blockIdx.x * blockDim.x + threadIdx.x) >> 5;
    int lane = threadIdx.x & 31;
    int e0 = w * 4;
    if (e0 >= NE) return;
    int s[4], d[4];
    bool ok[4];
#pragma unroll
    for (int e = 0; e < 4; e++) {
        s[e] = ei[e0 + e];
        d[e] = ei[NE + e0 + e];
        ok[e] = ((unsigned)s[e] < NN) && ((unsigned)d[e] < NN);
    }
    float4 v[4];
#pragma unroll
    for (int e = 0; e < 4; e++)
        if (ok[e])
            v[e] = *reinterpret_cast<const float4*>(x + (size_t)s[e] * C + lane * 4);
#pragma unroll
    for (int e = 0; e < 4; e++)
        if (ok[e])
            red_add_v4(g_agg + (size_t)r * NN * C + (size_t)d[e] * C + lane * 4, v[e]);
    if (lane < 4 && ok[lane])
        atomicAdd(&g_cnt[r * NN + d[lane]], 1.f);
}

// ---------------- fused pipelined fp16 WMMA GEMM (R12 measured) -------------
__global__ __launch_bounds__(256, 2)
void k_gemm_fused(const float* __restrict__ bl, const float* __restrict__ blf) {
    extern __shared__ char smraw[];
    __shared__ float bls[NREL * C + OC];
    __half* X_s = reinterpret_cast<__half*>(smraw);      // [64][HLD]
    __half* A_s = X_s + TM * HLD;                        // [64][HLD]
    float*  H32 = reinterpret_cast<float*>(smraw);       // [64][FLD] over X+A
    float*  Df  = reinterpret_cast<float*>(smraw);       // [64][FLD] over X+A
    __half* WfS = reinterpret_cast<__half*>(smraw + 2 * WHB);  // over buf0 [128][HLD]
    __half* Hh  = reinterpret_cast<__half*>(smraw + 4 * WHB);  // over buf1 [64][HLD]

    uint32_t base = smem_u32(smraw);
    uint32_t xa = base;
    uint32_t wb0 = base + 2 * WHB;
    uint32_t wb1 = base + 4 * WHB;

    int tid = threadIdx.x;
    int wid = tid >> 5;
    int node0 = blockIdx.x * TM;
    int wm = (wid >> 2) * 32;
    int wn = (wid & 3) * 32;

    for (int i = tid; i < NREL * C; i += 256) bls[i] = bl[i];
    if (tid < OC) bls[NREL * C + tid] = blf[tid];

    // prologue: X tile + W(step 0 = rel0 half0) into buf0
    for (int it = tid; it < TM * 16; it += 256) {
        int row = it >> 4, c = it & 15;
        int node = node0 + row;
        bool ok = node < NN;
        cpa16z(xa + row * (HLD * 2) + c * 16,
               g_xh + (size_t)(ok ? node : 0) * C + c * 8, ok);
    }
    for (int it = tid; it < 64 * 16; it += 256) {
        int row = it >> 4, c = it & 15;
        cpa16(wb0 + row * (HLD * 2) + c * 16, g_Whl + row * C + c * 8);
        cpa16(wb0 + WHB + row * (HLD * 2) + c * 16, g_Whr + row * C + c * 8);
    }
    CPA_COMMIT();

    wmma::fragment<wmma::accumulator, 16, 16, 16, float> iotaf;
    wmma::load_matrix_sync(iotaf, g_iota, 16, wmma::mem_row_major);

    wmma::fragment<wmma::accumulator, 16, 16, 16, float> hfrag[2][2];
#pragma unroll
    for (int i = 0; i < 2; i++)
#pragma unroll
        for (int j = 0; j < 2; j++) wmma::fill_fragment(hfrag[i][j], 0.f);
    const float inv3 = 1.f / 3.f;

    wmma::fragment<wmma::accumulator, 16, 16, 16, float> acc[2][2];

    for (int s = 0; s < 6; s++) {
        int r = s >> 1, h = s & 1;
        __half* WlS = reinterpret_cast<__half*>(smraw + 2 * WHB + (s & 1) * 2 * WHB);
        __half* WrS = WlS + 64 * HLD;

        __syncthreads();  // all warps done with previous step's MMAs

        if (s < 5) {
            int r2 = (s + 1) >> 1, h2 = (s + 1) & 1;
            const __half* wl = g_Whl + (size_t)r2 * C * C + h2 * 64 * C;
            const __half* wr = g_Whr + (size_t)r2 * C * C + h2 * 64 * C;
            uint32_t b = ((s + 1) & 1) ? wb1 : wb0;
            for (int it = tid; it < 64 * 16; it += 256) {
                int row = it >> 4, c = it & 15;
                cpa16(b + row * (HLD * 2) + c * 16, wl + row * C + c * 8);
                cpa16(b + WHB + row * (HLD * 2) + c * 16, wr + row * C + c * 8);
            }
        } else {
            for (int it = tid; it < 128 * 16; it += 256) {
                int row = it >> 4, c = it & 15;
                cpa16(wb0 + row * (HLD * 2) + c * 16, g_Whf + row * C + c * 8);
            }
        }
        CPA_COMMIT();

        if (h == 0) {
            const float* aggr = g_agg + (size_t)r * NN * C;
            const float* cntr = g_cnt + r * NN;
            float4 va[8];
            float  vc[8];
            bool   okr[8];
#pragma unroll
            for (int i = 0; i < 8; i++) {
                int idx = tid + i * 256;
                int row = idx >> 5, c4 = idx & 31;
                int node = node0 + row;
                okr[i] = node < NN;
                if (okr[i]) {
                    va[i] = *reinterpret_cast<const float4*>(
                        aggr + (size_t)node * C + c4 * 4);
                    vc[i] = cntr[node];
                }
            }
#pragma unroll
            for (int i = 0; i < 8; i++) {
                int idx = tid + i * 256;
                int row = idx >> 5, c4 = idx & 31;
                float4 v = make_float4(0.f, 0.f, 0.f, 0.f);
                if (okr[i]) {
                    float inv = 1.f / fmaxf(vc[i], 1.f);
                    v.x = va[i].x * inv; v.y = va[i].y * inv;
                    v.z = va[i].z * inv; v.w = va[i].w * inv;
                }
                __half2* dp = reinterpret_cast<__half2*>(A_s + row * HLD + c4 * 4);
                dp[0] = __floats2half2_rn(v.x, v.y);
                dp[1] = __floats2half2_rn(v.z, v.w);
            }
#pragma unroll
            for (int i = 0; i < 2; i++)
#pragma unroll
                for (int j = 0; j < 2; j++) wmma::fill_fragment(acc[i][j], 0.f);
        }

        CPA_WAIT1();
        __syncthreads();  // W + A visible to all warps

#pragma unroll
        for (int ks = 0; ks < 4; ks++) {
            int kloc = ks * 16;
            int kglb = h * 64 + kloc;
            wmma::fragment<wmma::matrix_a, 16, 16, 16, __half,
                           wmma::row_major> af[2], xf[2];
            wmma::fragment<wmma::matrix_b, 16, 16, 16, __half,
                           wmma::row_major> lf[2], rf[2];
#pragma unroll
            for (int i = 0; i < 2; i++) {
                wmma::load_matrix_sync(af[i], A_s + (wm + i * 16) * HLD + kglb, HLD);
                wmma::load_matrix_sync(xf[i], X_s + (wm + i * 16) * HLD + kglb, HLD);
            }
#pragma unroll
            for (int j = 0; j < 2; j++) {
                wmma::load_matrix_sync(lf[j], WlS + kloc * HLD + wn + j * 16, HLD);
                wmma::load_matrix_sync(rf[j], WrS + kloc * HLD + wn + j * 16, HLD);
            }
#pragma unroll
            for (int i = 0; i < 2; i++)
#pragma unroll
                for (int j = 0; j < 2; j++) {
                    wmma::mma_sync(acc[i][j], af[i], lf[j], acc[i][j]);
                    wmma::mma_sync(acc[i][j], xf[i], rf[j], acc[i][j]);
                }
        }

        if (h == 1) {
#pragma unroll
            for (int i = 0; i < 2; i++)
#pragma unroll
                for (int j = 0; j < 2; j++)
#pragma unroll
                    for (int t = 0; t < 8; t++) {
                        float b = bls[r * C + wn + j * 16 + (int)iotaf.x[t]];
                        hfrag[i][j].x[t] +=
                            fmaxf(acc[i][j].x[t] + b, 0.f) * inv3;
                    }
        }
    }

    // ---------------- final GEMM: D_f = h @ [Wlf | Wrf] ---------------------
    __syncthreads();
#pragma unroll
    for (int i = 0; i < 2; i++)
#pragma unroll
        for (int j = 0; j < 2; j++)
            wmma::store_matrix_sync(H32 + (wm + i * 16) * FLD + wn + j * 16,
                                    hfrag[i][j], FLD, wmma::mem_row_major);
    __syncthreads();
    for (int it = tid; it < TM * 64; it += 256) {
        int row = it >> 6, c2 = it & 63;
        float2 v = *reinterpret_cast<const float2*>(H32 + row * FLD + c2 * 2);
        *reinterpret_cast<__half2*>(Hh + row * HLD + c2 * 2) =
            __floats2half2_rn(v.x, v.y);
    }
    CPA_WAIT0();      // Wf (prefetched during step 5) in buf0
    __syncthreads();

    {
        wmma::fragment<wmma::accumulator, 16, 16, 16, float> acc2[2][2];
#pragma unroll
        for (int i = 0; i < 2; i++)
#pragma unroll
            for (int j = 0; j < 2; j++) wmma::fill_fragment(acc2[i][j], 0.f);

#pragma unroll
        for (int ks = 0; ks < 8; ks++) {
            int k = ks * 16;
            wmma::fragment<wmma::matrix_a, 16, 16, 16, __half,
                           wmma::row_major> hf[2];
            wmma::fragment<wmma::matrix_b, 16, 16, 16, __half,
                           wmma::row_major> wf[2];
#pragma unroll
            for (int i = 0; i < 2; i++)
                wmma::load_matrix_sync(hf[i], Hh + (wm + i * 16) * HLD + k, HLD);
#pragma unroll
            for (int j = 0; j < 2; j++)
                wmma::load_matrix_sync(wf[j], WfS + k * HLD + wn + j * 16, HLD);
#pragma unroll
            for (int i = 0; i < 2; i++)
#pragma unroll
                for (int j = 0; j < 2; j++)
                    wmma::mma_sync(acc2[i][j], hf[i], wf[j], acc2[i][j]);
        }
        __syncthreads();
#pragma unroll
        for (int i = 0; i < 2; i++)
#pragma unroll
            for (int j = 0; j < 2; j++)
                wmma::store_matrix_sync(Df + (wm + i * 16) * FLD + wn + j * 16,
                                        acc2[i][j], FLD, wmma::mem_row_major);
        __syncthreads();
    }

    // epilogue: t (cols 0..63), po (cols 64..127, +blf); zero aggF slice
    {
        int row = tid >> 2;
        int ec  = (tid & 3) * 32;
        int node = node0 + row;
        if (node < NN) {
            if (ec < OC) {
                float* tp = g_t + (size_t)node * OC + ec;
                float* zp = g_aggF + (size_t)node * OC + ec;
#pragma unroll
                for (int q = 0; q < 8; q++) {
                    *reinterpret_cast<float4*>(tp + q * 4) =
                        *reinterpret_cast<const float4*>(Df + row * FLD + ec + q * 4);
                    *reinterpret_cast<float4*>(zp + q * 4) =
                        make_float4(0.f, 0.f, 0.f, 0.f);
                }
            } else {
                float* pp = g_po + (size_t)node * OC + (ec - OC);
                float* zp = g_aggF + (size_t)node * OC + (ec - OC);
#pragma unroll
                for (int q = 0; q < 8; q++) {
                    float4 d = *reinterpret_cast<const float4*>(
                        Df + row * FLD + ec + q * 4);
                    const float* b = bls + NREL * C + (ec - OC) + q * 4;
                    *reinterpret_cast<float4*>(pp + q * 4) = make_float4(
                        d.x + b[0], d.y + b[1], d.z + b[2], d.w + b[3]);
                    *reinterpret_cast<float4*>(zp + q * 4) =
                        make_float4(0.f, 0.f, 0.f, 0.f);
                }
            }
        }
    }
}

// ---------------- kernel 4: scatter t, 4 edges per half-warp (R8 measured) --
__global__ void k_scatter_t(const int* __restrict__ ei) {
    int hw = (blockIdx.x * blockDim.x + threadIdx.x) >> 4;
    int lane = threadIdx.x & 15;
    int e0 = hw * 4;
    if (e0 >= NE) return;
    int s[4], d[4];
    bool ok[4];
#pragma unroll
    for (int e = 0; e < 4; e++) {
        s[e] = ei[e0 + e];
        d[e] = ei[NE + e0 + e];
        ok[e] = ((unsigned)s[e] < NN) && ((unsigned)d[e] < NN);
    }
    float4 v[4];
#pragma unroll
    for (int e = 0; e < 4; e++)
        if (ok[e])
            v[e] = *reinterpret_cast<const float4*>(g_t + (size_t)s[e] * OC + lane * 4);
#pragma unroll
    for (int e = 0; e < 4; e++)
        if (ok[e])
            red_add_v4(g_aggF + (size_t)d[e] * OC + lane * 4, v[e]);
}

// ---------------- kernel 5: out = aggF / max(cnt0,1) + po -------------------
__global__ void k_final(float* __restrict__ out) {
    int i = blockIdx.x * blockDim.x + threadIdx.x;
    int stride = gridDim.x * blockDim.x;
    int n4 = NN * OC / 4;
    const float4* a4 = reinterpret_cast<const float4*>(g_aggF);
    const float4* p4 = reinterpret_cast<const float4*>(g_po);
    float4* o4 = reinterpret_cast<float4*>(out);
    for (int j = i; j < n4; j += stride) {
        int node = j / (OC / 4);
        float inv = 1.f / fmaxf(g_cnt[node], 1.f);
        float4 a = a4[j];
        float4 p = p4[j];
        o4[j] = make_float4(a.x * inv + p.x, a.y * inv + p.y,
                            a.z * inv + p.z, a.w * inv + p.w);
    }
}

// ---------------- launch ----------------------------------------------------
extern "C" void kernel_launch(void* const* d_in, const int* in_sizes, int n_in,
                              void* d_out, int out_size) {
    const float* x   = (const float*)d_in[0];
    const float* Wl  = (const float*)d_in[1];
    const float* bl  = (const float*)d_in[2];
    const float* Wr  = (const float*)d_in[3];
    const float* Wlf = (const float*)d_in[4];
    const float* blf = (const float*)d_in[5];
    const float* Wrf = (const float*)d_in[6];
    const int* ei0   = (const int*)d_in[7];
    const int* ei1   = (const int*)d_in[8];
    const int* ei2   = (const int*)d_in[9];
    float* out = (float*)d_out;

    // Side stream + events (host objects only; created per call, never
    // destroyed mid-capture; kernel_launch executes host-side only twice).
    cudaStream_t s1;
    cudaEvent_t eFork, eJoin, eG, eZ;
    cudaStreamCreateWithFlags(&s1, cudaStreamNonBlocking);
    cudaEventCreateWithFlags(&eFork, cudaEventDisableTiming);
    cudaEventCreateWithFlags(&eJoin, cudaEventDisableTiming);
    cudaEventCreateWithFlags(&eG, cudaEventDisableTiming);
    cudaEventCreateWithFlags(&eZ, cudaEventDisableTiming);

    void *pagg, *pcnt;
    cudaGetSymbolAddress(&pagg, g_agg);
    cudaGetSymbolAddress(&pcnt, g_cnt);

    // fork: k_prep on s1, overlapped with scatter_x (g_agg/g_cnt already zero
    // — see invariant at the scratch declarations; no head memsets).
    cudaEventRecord(eFork, 0);
    cudaStreamWaitEvent(s1, eFork, 0);
    k_prep<<<1024, 256, 0, s1>>>(Wl, Wr, Wlf, Wrf, x);
    cudaEventRecord(eJoin, s1);

    dim3 sgrid((NE / 4 + 7) / 8, 3);
    k_scatter_x<<<sgrid, 256>>>(x, ei0, ei1, ei2);

    cudaStreamWaitEvent(0, eJoin, 0);  // gemm needs prep outputs

    const int SMEMF = 6 * WHB;  // X + A + 2 W half-buffers = 104448
    cudaFuncSetAttribute(k_gemm_fused, cudaFuncAttributeMaxDynamicSharedMemorySize, SMEMF);
    int gb = (NN + TM - 1) / TM;  // 1563
    k_gemm_fused<<<gb, 256, SMEMF>>>(bl, blf);

    // tail: re-zero g_agg on s1 (dead after gemm), hidden under scatter_t+final
    cudaEventRecord(eG, 0);
    cudaStreamWaitEvent(s1, eG, 0);
    cudaMemsetAsync(pagg, 0, (size_t)NREL * NN * C * sizeof(float), s1);
    cudaEventRecord(eZ, s1);

    k_scatter_t<<<(NE / 4 + 15) / 16, 256>>>(ei0);
    k_final<<<2048, 256>>>(out);
    // g_cnt is read by k_final -> re-zero only afterwards (1.2MB, ~1us)
    cudaMemsetAsync(pcnt, 0, (size_t)NREL * NN * sizeof(float), 0);
    cudaStreamWaitEvent(0, eZ, 0);  // join side stream before capture ends
}